// round 1
// baseline (speedup 1.0000x reference)
#include <cuda_runtime.h>
#include <math.h>

#define Bb 4
#define Ss 2048
#define Ee 1024
#define Hh 16
#define KVv 4
#define HDd 64
#define Rr 8
#define CDd 64
#define NQq 8
#define NCH 16
#define CHUNK 128
#define NTOK (Bb*Ss)      // 8192
#define NCAT 1600         // 64 + 3*512

// ---------------- scratch (device globals; no cudaMalloc allowed) ----------------
__device__ float g_Wcat[1024 * NCAT];
__device__ float g_bcat[NCAT];
__device__ float g_P[(size_t)NTOK * NCAT];
__device__ float g_v[(size_t)Bb * KVv * Ss * HDd];
__device__ float g_qf[(size_t)Bb * Hh * Ss * 16];
__device__ float g_kf[(size_t)Bb * KVv * Ss * 16];
__device__ float g_kvc[(size_t)Bb * KVv * NCH * 16 * 64];
__device__ float g_kvp[(size_t)Bb * KVv * NCH * 16 * 64];
__device__ float g_kfc[Bb * KVv * NCH * 16];
__device__ float g_kfp[Bb * KVv * NCH * 16];
__device__ float g_attn[(size_t)NTOK * Ee];

// ---------------- helpers ----------------
__device__ __forceinline__ void ld16(float* o, const float4* p) {
    float4 a = __ldg(p + 0), b = __ldg(p + 1), c = __ldg(p + 2), d = __ldg(p + 3);
    o[0] = a.x;  o[1] = a.y;  o[2] = a.z;  o[3] = a.w;
    o[4] = b.x;  o[5] = b.y;  o[6] = b.z;  o[7] = b.w;
    o[8] = c.x;  o[9] = c.y;  o[10] = c.z; o[11] = c.w;
    o[12] = d.x; o[13] = d.y; o[14] = d.z; o[15] = d.w;
}

// ---------------- K0: pack concatenated weights/bias ----------------
__global__ void pack_kernel(const float* __restrict__ ctxW, const float* __restrict__ qaW,
                            const float* __restrict__ kaW,  const float* __restrict__ vaW,
                            const float* __restrict__ ctxb, const float* __restrict__ qab,
                            const float* __restrict__ kab,  const float* __restrict__ vab) {
    const int total = 1024 * NCAT;
    for (int i = blockIdx.x * blockDim.x + threadIdx.x; i < total; i += gridDim.x * blockDim.x) {
        int e = i / NCAT, c = i % NCAT;
        float v;
        if (c < 64)        v = ctxW[e * 64 + c];
        else if (c < 576)  v = qaW[e * 512 + (c - 64)];
        else if (c < 1088) v = kaW[e * 512 + (c - 576)];
        else               v = vaW[e * 512 + (c - 1088)];
        g_Wcat[i] = v;
    }
    int j = blockIdx.x * blockDim.x + threadIdx.x;
    if (j < NCAT) {
        float v;
        if (j < 64)        v = ctxb[j];
        else if (j < 576)  v = qab[j - 64];
        else if (j < 1088) v = kab[j - 576];
        else               v = vab[j - 1088];
        g_bcat[j] = v;
    }
}

// ---------------- SGEMM body: C[M,N] = A[M,K] @ B[K,N] + bias (+ res) ----------------
// BM=BN=128, BK=16, 256 threads, 8x8 per thread. M%128==0, K%16==0 assumed; N guarded.
__device__ __forceinline__ void sgemm_body(int M, int N, int K,
                                           const float* __restrict__ A,
                                           const float* __restrict__ Bm,
                                           const float* __restrict__ bias,
                                           const float* __restrict__ res,
                                           float* __restrict__ C) {
    __shared__ float As[16][128];
    __shared__ float Bs[16][128];
    const int bm = blockIdx.y * 128, bn = blockIdx.x * 128;
    const int tid = threadIdx.x;
    const int tx = (tid & 15) * 8;
    const int ty = (tid >> 4) * 8;
    float acc[8][8];
#pragma unroll
    for (int i = 0; i < 8; i++)
#pragma unroll
        for (int j = 0; j < 8; j++) acc[i][j] = 0.f;

    for (int k0 = 0; k0 < K; k0 += 16) {
#pragma unroll
        for (int i = 0; i < 2; i++) {
            int idx = tid + i * 256;           // 512 float4 slots of the 128x16 A tile
            int m = idx >> 2;
            int kk = (idx & 3) * 4;
            float4 va = *reinterpret_cast<const float4*>(&A[(size_t)(bm + m) * K + k0 + kk]);
            As[kk + 0][m] = va.x; As[kk + 1][m] = va.y;
            As[kk + 2][m] = va.z; As[kk + 3][m] = va.w;
        }
#pragma unroll
        for (int i = 0; i < 2; i++) {
            int idx = tid + i * 256;           // 16 rows x 32 float4 of the B tile
            int kk = idx >> 5;
            int n = (idx & 31) * 4;
            int gn = bn + n;
            float4 vb = make_float4(0.f, 0.f, 0.f, 0.f);
            if (gn < N) vb = *reinterpret_cast<const float4*>(&Bm[(size_t)(k0 + kk) * N + gn]);
            Bs[kk][n + 0] = vb.x; Bs[kk][n + 1] = vb.y;
            Bs[kk][n + 2] = vb.z; Bs[kk][n + 3] = vb.w;
        }
        __syncthreads();
#pragma unroll
        for (int kk = 0; kk < 16; kk++) {
            float af[8], bfv[8];
#pragma unroll
            for (int i = 0; i < 8; i++) af[i] = As[kk][ty + i];
#pragma unroll
            for (int j = 0; j < 8; j++) bfv[j] = Bs[kk][tx + j];
#pragma unroll
            for (int i = 0; i < 8; i++)
#pragma unroll
                for (int j = 0; j < 8; j++) acc[i][j] += af[i] * bfv[j];
        }
        __syncthreads();
    }
#pragma unroll
    for (int i = 0; i < 8; i++) {
        int gm = bm + ty + i;
#pragma unroll
        for (int j = 0; j < 8; j++) {
            int gn = bn + tx + j;
            if (gn < N) {
                float v = acc[i][j] + bias[gn];
                if (res) v += res[(size_t)gm * N + gn];
                C[(size_t)gm * N + gn] = v;
            }
        }
    }
}

__global__ __launch_bounds__(256, 2)
void gemm1_kernel(const float* __restrict__ x) {
    sgemm_body(NTOK, NCAT, Ee, x, g_Wcat, g_bcat, nullptr, g_P);
}

__global__ __launch_bounds__(256, 2)
void gemm2_kernel(const float* __restrict__ outW, const float* __restrict__ outb,
                  const float* __restrict__ x, float* __restrict__ out) {
    sgemm_body(NTOK, Ee, Ee, g_attn, outW, outb, x, out);
}

// ---------------- K2: fused b-factors + TPA contraction + quantum features ----------------
__global__ __launch_bounds__(256, 4)
void tpa_feat_kernel(const float* __restrict__ qbW, const float* __restrict__ qbb,
                     const float* __restrict__ kbW, const float* __restrict__ kbb,
                     const float* __restrict__ vbW, const float* __restrict__ vbb,
                     const float* __restrict__ qeW, const float* __restrict__ qeb,
                     const float* __restrict__ vqc, const float* __restrict__ ent) {
    __shared__ float sP[NCAT];
    __shared__ float sQB[128], sKB[32], sVB[32];
    __shared__ float sQ[1024];
    __shared__ float sK[256];
    const int token = blockIdx.x;
    const int b = token / Ss, s = token % Ss;
    const int tid = threadIdx.x;

    const float4* p4 = reinterpret_cast<const float4*>(&g_P[(size_t)token * NCAT]);
    for (int i = tid; i < NCAT / 4; i += 256) reinterpret_cast<float4*>(sP)[i] = p4[i];
    __syncthreads();

    // b-factors from ctx (sP[0:64])
    if (tid < 128) {
        float a = qbb[tid];
#pragma unroll
        for (int c = 0; c < 64; c++) a += sP[c] * qbW[c * 128 + tid];
        sQB[tid] = a;
    } else if (tid < 160) {
        int t = tid - 128; float a = kbb[t];
#pragma unroll
        for (int c = 0; c < 64; c++) a += sP[c] * kbW[c * 32 + t];
        sKB[t] = a;
    } else if (tid < 192) {
        int t = tid - 160; float a = vbb[t];
#pragma unroll
        for (int c = 0; c < 64; c++) a += sP[c] * vbW[c * 32 + t];
        sVB[t] = a;
    }
    __syncthreads();

    // TPA contraction: q[h,d], k[kv,d] -> smem; v[kv,d] -> gmem
    for (int o = tid; o < 1024; o += 256) {
        int h = o >> 6, d = o & 63;
        float a = 0.f;
#pragma unroll
        for (int r = 0; r < 8; r++) a += sP[64 + r * 64 + d] * sQB[r * 16 + h];
        sQ[o] = a;
    }
    if (tid < 256) {
        int kv = tid >> 6, d = tid & 63;
        float ak = 0.f, av = 0.f;
#pragma unroll
        for (int r = 0; r < 8; r++) {
            ak += sP[576 + r * 64 + d] * sKB[r * 4 + kv];
            av += sP[1088 + r * 64 + d] * sVB[r * 4 + kv];
        }
        sK[tid] = ak;
        g_v[(((size_t)(b * KVv + kv)) * Ss + s) * 64 + d] = av;
    }
    __syncthreads();

    // quantum features: 20 heads (16 q + 4 k), one warp per head
    const int warp = tid >> 5, lane = tid & 31;
    const float ev = __ldg(ent);
    for (int head = warp; head < 20; head += 8) {
        const float* src = head < 16 ? &sQ[head * 64] : &sK[(head - 16) * 64];
        float x0 = src[lane], x1 = src[lane + 32];
        float p[8];
#pragma unroll
        for (int j = 0; j < 8; j++)
            p[j] = x0 * __ldg(&qeW[lane * 8 + j]) + x1 * __ldg(&qeW[(lane + 32) * 8 + j]);
#pragma unroll
        for (int off = 16; off; off >>= 1)
#pragma unroll
            for (int j = 0; j < 8; j++) p[j] += __shfl_xor_sync(0xffffffffu, p[j], off);
        float f[8];
#pragma unroll
        for (int j = 0; j < 8; j++) f[j] = tanhf(p[j] + __ldg(&qeb[j])) * 3.14159265358979323846f;
#pragma unroll
        for (int l = 0; l < 2; l++) {
            float g[8];
#pragma unroll
            for (int j = 0; j < 8; j++) {
                float a0 = __ldg(&vqc[(l * 8 + j) * 3 + 0]);
                float a1 = __ldg(&vqc[(l * 8 + j) * 3 + 1]);
                float a2 = __ldg(&vqc[(l * 8 + j) * 3 + 2]);
                g[j] = cosf(f[j] + a0) * sinf(f[j] + a1) + cosf(f[j] + a2);
            }
#pragma unroll
            for (int j = 0; j < 8; j++) f[j] = g[j] * (1.f + ev * g[(j + 7) & 7]);
        }
        float cs[16]; float nrm = 0.f;
#pragma unroll
        for (int j = 0; j < 8; j++) { cs[j] = cosf(f[j]); cs[j + 8] = sinf(f[j]); }
#pragma unroll
        for (int j = 0; j < 16; j++) nrm += cs[j] * cs[j];
        float inv = 1.f / (sqrtf(nrm) + 1e-6f);
        if (lane < 16) {
            float* dst = head < 16
                ? &g_qf[(((size_t)(b * Hh + head)) * Ss + s) * 16]
                : &g_kf[(((size_t)(b * KVv + (head - 16))) * Ss + s) * 16];
            dst[lane] = cs[lane] * inv;
        }
    }
}

// ---------------- Pass A: per-chunk sums of kf (x) v and kf ----------------
__global__ __launch_bounds__(64, 8)
void passA_kernel() {
    const int blk = blockIdx.x;            // (b*KV+kv)*NCH + c
    const int c = blk % NCH;
    const int bk = blk / NCH;
    const int tid = threadIdx.x;           // d
    const float4* kfb = reinterpret_cast<const float4*>(&g_kf[(((size_t)bk) * Ss + c * CHUNK) * 16]);
    const float* vb = &g_v[(((size_t)bk) * Ss + c * CHUNK) * 64];
    float acc[16];
#pragma unroll
    for (int f = 0; f < 16; f++) acc[f] = 0.f;
    float kfs = 0.f;
    for (int t = 0; t < CHUNK; t++) {
        float vd = vb[t * 64 + tid];
        float kv[16]; ld16(kv, kfb + t * 4);
#pragma unroll
        for (int f = 0; f < 16; f++) acc[f] += kv[f] * vd;
        if (tid < 16) kfs += __ldg(&g_kf[(((size_t)bk) * Ss + c * CHUNK + t) * 16 + tid]);
    }
#pragma unroll
    for (int f = 0; f < 16; f++) g_kvc[((size_t)blk * 16 + f) * 64 + tid] = acc[f];
    if (tid < 16) g_kfc[blk * 16 + tid] = kfs;
}

// ---------------- Pass B: exclusive prefix over chunks ----------------
__global__ __launch_bounds__(64, 8)
void passB_kernel() {
    const int bk = blockIdx.x;             // b*KV+kv
    const int tid = threadIdx.x;
    float run[16];
#pragma unroll
    for (int f = 0; f < 16; f++) run[f] = 0.f;
    float rk = 0.f;
    for (int c = 0; c < NCH; c++) {
        int blk = bk * NCH + c;
#pragma unroll
        for (int f = 0; f < 16; f++) {
            g_kvp[((size_t)blk * 16 + f) * 64 + tid] = run[f];
            run[f] += g_kvc[((size_t)blk * 16 + f) * 64 + tid];
        }
        if (tid < 16) { g_kfp[blk * 16 + tid] = rk; rk += g_kfc[blk * 16 + tid]; }
    }
}

// ---------------- Pass C: within-chunk scan + query eval for 4 heads ----------------
__global__ __launch_bounds__(64, 8)
void passC_kernel() {
    const int blk = blockIdx.x;
    const int c = blk % NCH;
    const int bk = blk / NCH;
    const int b = bk / KVv, kvh = bk % KVv;
    const int tid = threadIdx.x;           // d
    float st[16], kc[16];
#pragma unroll
    for (int f = 0; f < 16; f++) {
        st[f] = g_kvp[((size_t)blk * 16 + f) * 64 + tid];
        kc[f] = __ldg(&g_kfp[blk * 16 + f]);
    }
    const float4* kfb = reinterpret_cast<const float4*>(&g_kf[(((size_t)bk) * Ss + c * CHUNK) * 16]);
    const float* vb = &g_v[(((size_t)bk) * Ss + c * CHUNK) * 64];
    const int h0 = kvh * 4;                // q heads h map to kv head h/4
    const float4* qfb[4];
#pragma unroll
    for (int hh = 0; hh < 4; hh++)
        qfb[hh] = reinterpret_cast<const float4*>(&g_qf[(((size_t)(b * Hh + h0 + hh)) * Ss + c * CHUNK) * 16]);
    float* ab = &g_attn[((size_t)b * Ss + c * CHUNK) * Ee + h0 * 64 + tid];

    for (int t = 0; t < CHUNK; t++) {
        float vd = vb[t * 64 + tid];
        float kv[16]; ld16(kv, kfb + t * 4);
#pragma unroll
        for (int f = 0; f < 16; f++) { st[f] += kv[f] * vd; kc[f] += kv[f]; }
#pragma unroll
        for (int hh = 0; hh < 4; hh++) {
            float qv[16]; ld16(qv, qfb[hh] + t * 4);
            float num = 0.f, den = 0.f;
#pragma unroll
            for (int f = 0; f < 16; f++) { num += qv[f] * st[f]; den += qv[f] * kc[f]; }
            ab[(size_t)t * Ee + hh * 64] = num / (den + 1e-6f);
        }
    }
}

// ---------------- LayerNorm (in-place on d_out) ----------------
__global__ __launch_bounds__(256, 4)
void ln_kernel(float* __restrict__ y, const float* __restrict__ gamma, const float* __restrict__ beta) {
    const int row = blockIdx.x, tid = threadIdx.x;
    float4* yr = reinterpret_cast<float4*>(y + (size_t)row * Ee);
    float4 v = yr[tid];
    float s = v.x + v.y + v.z + v.w;
    float q = v.x * v.x + v.y * v.y + v.z * v.z + v.w * v.w;
    __shared__ float sS[8], sQ[8];
    const int lane = tid & 31, wid = tid >> 5;
#pragma unroll
    for (int off = 16; off; off >>= 1) {
        s += __shfl_xor_sync(0xffffffffu, s, off);
        q += __shfl_xor_sync(0xffffffffu, q, off);
    }
    if (lane == 0) { sS[wid] = s; sQ[wid] = q; }
    __syncthreads();
    if (tid == 0) {
        float ts = 0.f, tq = 0.f;
#pragma unroll
        for (int i = 0; i < 8; i++) { ts += sS[i]; tq += sQ[i]; }
        sS[0] = ts; sQ[0] = tq;
    }
    __syncthreads();
    float mu = sS[0] * (1.f / 1024.f);
    float var = sQ[0] * (1.f / 1024.f) - mu * mu;
    float rstd = rsqrtf(var + 1e-5f);
    const float4 gm = reinterpret_cast<const float4*>(gamma)[tid];
    const float4 bt = reinterpret_cast<const float4*>(beta)[tid];
    float4 o;
    o.x = gm.x * (v.x - mu) * rstd + bt.x;
    o.y = gm.y * (v.y - mu) * rstd + bt.y;
    o.z = gm.z * (v.z - mu) * rstd + bt.z;
    o.w = gm.w * (v.w - mu) * rstd + bt.w;
    yr[tid] = o;
}

// ---------------- launch ----------------
extern "C" void kernel_launch(void* const* d_in, const int* in_sizes, int n_in,
                              void* d_out, int out_size) {
    const float* x    = (const float*)d_in[0];
    const float* ctxW = (const float*)d_in[1];
    const float* ctxb = (const float*)d_in[2];
    const float* qaW  = (const float*)d_in[3];
    const float* qab  = (const float*)d_in[4];
    const float* qbW  = (const float*)d_in[5];
    const float* qbb  = (const float*)d_in[6];
    const float* kaW  = (const float*)d_in[7];
    const float* kab  = (const float*)d_in[8];
    const float* kbW  = (const float*)d_in[9];
    const float* kbb  = (const float*)d_in[10];
    const float* vaW  = (const float*)d_in[11];
    const float* vab  = (const float*)d_in[12];
    const float* vbW  = (const float*)d_in[13];
    const float* vbb  = (const float*)d_in[14];
    const float* qeW  = (const float*)d_in[15];
    const float* qeb  = (const float*)d_in[16];
    const float* vqc  = (const float*)d_in[17];
    const float* ent  = (const float*)d_in[18];
    const float* outW = (const float*)d_in[19];
    const float* outb = (const float*)d_in[20];
    const float* gamma = (const float*)d_in[21];
    const float* beta  = (const float*)d_in[22];
    float* out = (float*)d_out;

    pack_kernel<<<512, 256>>>(ctxW, qaW, kaW, vaW, ctxb, qab, kab, vab);

    dim3 g1((NCAT + 127) / 128, NTOK / 128);
    gemm1_kernel<<<g1, 256>>>(x);

    tpa_feat_kernel<<<NTOK, 256>>>(qbW, qbb, kbW, kbb, vbW, vbb, qeW, qeb, vqc, ent);

    passA_kernel<<<Bb * KVv * NCH, 64>>>();
    passB_kernel<<<Bb * KVv, 64>>>();
    passC_kernel<<<Bb * KVv * NCH, 64>>>();

    dim3 g2(Ee / 128, NTOK / 128);
    gemm2_kernel<<<g2, 256>>>(outW, outb, x, out);

    ln_kernel<<<NTOK, 256>>>(out, gamma, beta);
}

// round 2
// speedup vs baseline: 1.0047x; 1.0047x over previous
#include <cuda_runtime.h>
#include <math.h>

#define Bb 4
#define Ss 2048
#define Ee 1024
#define Hh 16
#define KVv 4
#define HDd 64
#define Rr 8
#define CDd 64
#define NQq 8
#define NCH 16
#define CHUNK 128
#define NTOK (Bb*Ss)      // 8192
#define NCAT 1600         // 64 + 3*512

// ---------------- scratch (device globals; no cudaMalloc allowed) ----------------
__device__ float g_Wcat[1024 * NCAT];
__device__ float g_bcat[NCAT];
__device__ float g_P[(size_t)NTOK * NCAT];
__device__ float g_v[(size_t)Bb * KVv * Ss * HDd];
__device__ float g_qf[(size_t)Bb * Hh * Ss * 16];
__device__ float g_kf[(size_t)Bb * KVv * Ss * 16];
__device__ float g_kvc[(size_t)Bb * KVv * NCH * 16 * 64];
__device__ float g_kvp[(size_t)Bb * KVv * NCH * 16 * 64];
__device__ float g_kfc[Bb * KVv * NCH * 16];
__device__ float g_kfp[Bb * KVv * NCH * 16];
__device__ float g_attn[(size_t)NTOK * Ee];

// ---------------- helpers ----------------
__device__ __forceinline__ void ld16(float* o, const float4* p) {
    float4 a = __ldg(p + 0), b = __ldg(p + 1), c = __ldg(p + 2), d = __ldg(p + 3);
    o[0] = a.x;  o[1] = a.y;  o[2] = a.z;  o[3] = a.w;
    o[4] = b.x;  o[5] = b.y;  o[6] = b.z;  o[7] = b.w;
    o[8] = c.x;  o[9] = c.y;  o[10] = c.z; o[11] = c.w;
    o[12] = d.x; o[13] = d.y; o[14] = d.z; o[15] = d.w;
}

// ---------------- K0: pack concatenated weights/bias ----------------
__global__ void pack_kernel(const float* __restrict__ ctxW, const float* __restrict__ qaW,
                            const float* __restrict__ kaW,  const float* __restrict__ vaW,
                            const float* __restrict__ ctxb, const float* __restrict__ qab,
                            const float* __restrict__ kab,  const float* __restrict__ vab) {
    const int total = 1024 * NCAT;
    for (int i = blockIdx.x * blockDim.x + threadIdx.x; i < total; i += gridDim.x * blockDim.x) {
        int e = i / NCAT, c = i % NCAT;
        float v;
        if (c < 64)        v = ctxW[e * 64 + c];
        else if (c < 576)  v = qaW[e * 512 + (c - 64)];
        else if (c < 1088) v = kaW[e * 512 + (c - 576)];
        else               v = vaW[e * 512 + (c - 1088)];
        g_Wcat[i] = v;
    }
    int j = blockIdx.x * blockDim.x + threadIdx.x;
    if (j < NCAT) {
        float v;
        if (j < 64)        v = ctxb[j];
        else if (j < 576)  v = qab[j - 64];
        else if (j < 1088) v = kab[j - 576];
        else               v = vab[j - 1088];
        g_bcat[j] = v;
    }
}

// ---------------- SGEMM body: C[M,N] = A[M,K] @ B[K,N] + bias (+ res) ----------------
// BM=BN=128, BK=16, 256 threads, 8x8 per thread. M%128==0, K%16==0 assumed; N guarded.
__device__ __forceinline__ void sgemm_body(int M, int N, int K,
                                           const float* __restrict__ A,
                                           const float* __restrict__ Bm,
                                           const float* __restrict__ bias,
                                           const float* __restrict__ res,
                                           float* __restrict__ C) {
    __shared__ float As[16][128];
    __shared__ float Bs[16][128];
    const int bm = blockIdx.y * 128, bn = blockIdx.x * 128;
    const int tid = threadIdx.x;
    const int tx = (tid & 15) * 8;
    const int ty = (tid >> 4) * 8;
    float acc[8][8];
#pragma unroll
    for (int i = 0; i < 8; i++)
#pragma unroll
        for (int j = 0; j < 8; j++) acc[i][j] = 0.f;

    for (int k0 = 0; k0 < K; k0 += 16) {
#pragma unroll
        for (int i = 0; i < 2; i++) {
            int idx = tid + i * 256;           // 512 float4 slots of the 128x16 A tile
            int m = idx >> 2;
            int kk = (idx & 3) * 4;
            float4 va = *reinterpret_cast<const float4*>(&A[(size_t)(bm + m) * K + k0 + kk]);
            As[kk + 0][m] = va.x; As[kk + 1][m] = va.y;
            As[kk + 2][m] = va.z; As[kk + 3][m] = va.w;
        }
#pragma unroll
        for (int i = 0; i < 2; i++) {
            int idx = tid + i * 256;           // 16 rows x 32 float4 of the B tile
            int kk = idx >> 5;
            int n = (idx & 31) * 4;
            int gn = bn + n;
            float4 vb = make_float4(0.f, 0.f, 0.f, 0.f);
            if (gn < N) vb = *reinterpret_cast<const float4*>(&Bm[(size_t)(k0 + kk) * N + gn]);
            Bs[kk][n + 0] = vb.x; Bs[kk][n + 1] = vb.y;
            Bs[kk][n + 2] = vb.z; Bs[kk][n + 3] = vb.w;
        }
        __syncthreads();
#pragma unroll
        for (int kk = 0; kk < 16; kk++) {
            float af[8], bfv[8];
#pragma unroll
            for (int i = 0; i < 8; i++) af[i] = As[kk][ty + i];
#pragma unroll
            for (int j = 0; j < 8; j++) bfv[j] = Bs[kk][tx + j];
#pragma unroll
            for (int i = 0; i < 8; i++)
#pragma unroll
                for (int j = 0; j < 8; j++) acc[i][j] += af[i] * bfv[j];
        }
        __syncthreads();
    }
#pragma unroll
    for (int i = 0; i < 8; i++) {
        int gm = bm + ty + i;
#pragma unroll
        for (int j = 0; j < 8; j++) {
            int gn = bn + tx + j;
            if (gn < N) {
                float v = acc[i][j] + bias[gn];
                if (res) v += res[(size_t)gm * N + gn];
                C[(size_t)gm * N + gn] = v;
            }
        }
    }
}

__global__ __launch_bounds__(256, 2)
void gemm1_kernel(const float* __restrict__ x) {
    sgemm_body(NTOK, NCAT, Ee, x, g_Wcat, g_bcat, nullptr, g_P);
}

__global__ __launch_bounds__(256, 2)
void gemm2_kernel(const float* __restrict__ outW, const float* __restrict__ outb,
                  const float* __restrict__ x, float* __restrict__ out) {
    sgemm_body(NTOK, Ee, Ee, g_attn, outW, outb, x, out);
}

// ---------------- K2: fused b-factors + TPA contraction + quantum features ----------------
__global__ __launch_bounds__(256, 4)
void tpa_feat_kernel(const float* __restrict__ qbW, const float* __restrict__ qbb,
                     const float* __restrict__ kbW, const float* __restrict__ kbb,
                     const float* __restrict__ vbW, const float* __restrict__ vbb,
                     const float* __restrict__ qeW, const float* __restrict__ qeb,
                     const float* __restrict__ vqc, const float* __restrict__ ent) {
    __shared__ float sP[NCAT];
    __shared__ float sQB[128], sKB[32], sVB[32];
    __shared__ float sQ[1024];
    __shared__ float sK[256];
    const int token = blockIdx.x;
    const int b = token / Ss, s = token % Ss;
    const int tid = threadIdx.x;

    const float4* p4 = reinterpret_cast<const float4*>(&g_P[(size_t)token * NCAT]);
    for (int i = tid; i < NCAT / 4; i += 256) reinterpret_cast<float4*>(sP)[i] = p4[i];
    __syncthreads();

    // b-factors from ctx (sP[0:64])
    if (tid < 128) {
        float a = qbb[tid];
#pragma unroll
        for (int c = 0; c < 64; c++) a += sP[c] * qbW[c * 128 + tid];
        sQB[tid] = a;
    } else if (tid < 160) {
        int t = tid - 128; float a = kbb[t];
#pragma unroll
        for (int c = 0; c < 64; c++) a += sP[c] * kbW[c * 32 + t];
        sKB[t] = a;
    } else if (tid < 192) {
        int t = tid - 160; float a = vbb[t];
#pragma unroll
        for (int c = 0; c < 64; c++) a += sP[c] * vbW[c * 32 + t];
        sVB[t] = a;
    }
    __syncthreads();

    // TPA contraction: q[h,d], k[kv,d] -> smem; v[kv,d] -> gmem
    for (int o = tid; o < 1024; o += 256) {
        int h = o >> 6, d = o & 63;
        float a = 0.f;
#pragma unroll
        for (int r = 0; r < 8; r++) a += sP[64 + r * 64 + d] * sQB[r * 16 + h];
        sQ[o] = a;
    }
    if (tid < 256) {
        int kv = tid >> 6, d = tid & 63;
        float ak = 0.f, av = 0.f;
#pragma unroll
        for (int r = 0; r < 8; r++) {
            ak += sP[576 + r * 64 + d] * sKB[r * 4 + kv];
            av += sP[1088 + r * 64 + d] * sVB[r * 4 + kv];
        }
        sK[tid] = ak;
        g_v[(((size_t)(b * KVv + kv)) * Ss + s) * 64 + d] = av;
    }
    __syncthreads();

    // quantum features: 20 heads (16 q + 4 k), one warp per head
    const int warp = tid >> 5, lane = tid & 31;
    const float ev = __ldg(ent);
    for (int head = warp; head < 20; head += 8) {
        const float* src = head < 16 ? &sQ[head * 64] : &sK[(head - 16) * 64];
        float x0 = src[lane], x1 = src[lane + 32];
        float p[8];
#pragma unroll
        for (int j = 0; j < 8; j++)
            p[j] = x0 * __ldg(&qeW[lane * 8 + j]) + x1 * __ldg(&qeW[(lane + 32) * 8 + j]);
#pragma unroll
        for (int off = 16; off; off >>= 1)
#pragma unroll
            for (int j = 0; j < 8; j++) p[j] += __shfl_xor_sync(0xffffffffu, p[j], off);
        float f[8];
#pragma unroll
        for (int j = 0; j < 8; j++) f[j] = tanhf(p[j] + __ldg(&qeb[j])) * 3.14159265358979323846f;
#pragma unroll
        for (int l = 0; l < 2; l++) {
            float g[8];
#pragma unroll
            for (int j = 0; j < 8; j++) {
                float a0 = __ldg(&vqc[(l * 8 + j) * 3 + 0]);
                float a1 = __ldg(&vqc[(l * 8 + j) * 3 + 1]);
                float a2 = __ldg(&vqc[(l * 8 + j) * 3 + 2]);
                g[j] = cosf(f[j] + a0) * sinf(f[j] + a1) + cosf(f[j] + a2);
            }
#pragma unroll
            for (int j = 0; j < 8; j++) f[j] = g[j] * (1.f + ev * g[(j + 7) & 7]);
        }
        float cs[16]; float nrm = 0.f;
#pragma unroll
        for (int j = 0; j < 8; j++) { cs[j] = cosf(f[j]); cs[j + 8] = sinf(f[j]); }
#pragma unroll
        for (int j = 0; j < 16; j++) nrm += cs[j] * cs[j];
        float inv = 1.f / (sqrtf(nrm) + 1e-6f);
        if (lane < 16) {
            float* dst = head < 16
                ? &g_qf[(((size_t)(b * Hh + head)) * Ss + s) * 16]
                : &g_kf[(((size_t)(b * KVv + (head - 16))) * Ss + s) * 16];
            dst[lane] = cs[lane] * inv;
        }
    }
}

// ---------------- Pass A: per-chunk sums of kf (x) v and kf ----------------
__global__ __launch_bounds__(64, 8)
void passA_kernel() {
    const int blk = blockIdx.x;            // (b*KV+kv)*NCH + c
    const int c = blk % NCH;
    const int bk = blk / NCH;
    const int tid = threadIdx.x;           // d
    const float4* kfb = reinterpret_cast<const float4*>(&g_kf[(((size_t)bk) * Ss + c * CHUNK) * 16]);
    const float* vb = &g_v[(((size_t)bk) * Ss + c * CHUNK) * 64];
    float acc[16];
#pragma unroll
    for (int f = 0; f < 16; f++) acc[f] = 0.f;
    float kfs = 0.f;
    for (int t = 0; t < CHUNK; t++) {
        float vd = vb[t * 64 + tid];
        float kv[16]; ld16(kv, kfb + t * 4);
#pragma unroll
        for (int f = 0; f < 16; f++) acc[f] += kv[f] * vd;
        if (tid < 16) kfs += __ldg(&g_kf[(((size_t)bk) * Ss + c * CHUNK + t) * 16 + tid]);
    }
#pragma unroll
    for (int f = 0; f < 16; f++) g_kvc[((size_t)blk * 16 + f) * 64 + tid] = acc[f];
    if (tid < 16) g_kfc[blk * 16 + tid] = kfs;
}

// ---------------- Pass B: exclusive prefix over chunks ----------------
__global__ __launch_bounds__(64, 8)
void passB_kernel() {
    const int bk = blockIdx.x;             // b*KV+kv
    const int tid = threadIdx.x;
    float run[16];
#pragma unroll
    for (int f = 0; f < 16; f++) run[f] = 0.f;
    float rk = 0.f;
    for (int c = 0; c < NCH; c++) {
        int blk = bk * NCH + c;
#pragma unroll
        for (int f = 0; f < 16; f++) {
            g_kvp[((size_t)blk * 16 + f) * 64 + tid] = run[f];
            run[f] += g_kvc[((size_t)blk * 16 + f) * 64 + tid];
        }
        if (tid < 16) { g_kfp[blk * 16 + tid] = rk; rk += g_kfc[blk * 16 + tid]; }
    }
}

// ---------------- Pass C: within-chunk scan + query eval for 4 heads ----------------
__global__ __launch_bounds__(64, 8)
void passC_kernel() {
    const int blk = blockIdx.x;
    const int c = blk % NCH;
    const int bk = blk / NCH;
    const int b = bk / KVv, kvh = bk % KVv;
    const int tid = threadIdx.x;           // d
    float st[16], kc[16];
#pragma unroll
    for (int f = 0; f < 16; f++) {
        st[f] = g_kvp[((size_t)blk * 16 + f) * 64 + tid];
        kc[f] = __ldg(&g_kfp[blk * 16 + f]);
    }
    const float4* kfb = reinterpret_cast<const float4*>(&g_kf[(((size_t)bk) * Ss + c * CHUNK) * 16]);
    const float* vb = &g_v[(((size_t)bk) * Ss + c * CHUNK) * 64];
    const int h0 = kvh * 4;                // q heads h map to kv head h/4
    const float4* qfb[4];
#pragma unroll
    for (int hh = 0; hh < 4; hh++)
        qfb[hh] = reinterpret_cast<const float4*>(&g_qf[(((size_t)(b * Hh + h0 + hh)) * Ss + c * CHUNK) * 16]);
    float* ab = &g_attn[((size_t)b * Ss + c * CHUNK) * Ee + h0 * 64 + tid];

    for (int t = 0; t < CHUNK; t++) {
        float vd = vb[t * 64 + tid];
        float kv[16]; ld16(kv, kfb + t * 4);
#pragma unroll
        for (int f = 0; f < 16; f++) { st[f] += kv[f] * vd; kc[f] += kv[f]; }
#pragma unroll
        for (int hh = 0; hh < 4; hh++) {
            float qv[16]; ld16(qv, qfb[hh] + t * 4);
            float num = 0.f, den = 0.f;
#pragma unroll
            for (int f = 0; f < 16; f++) { num += qv[f] * st[f]; den += qv[f] * kc[f]; }
            ab[(size_t)t * Ee + hh * 64] = num / (den + 1e-6f);
        }
    }
}

// ---------------- LayerNorm (in-place on d_out) ----------------
__global__ __launch_bounds__(256, 4)
void ln_kernel(float* __restrict__ y, const float* __restrict__ gamma, const float* __restrict__ beta) {
    const int row = blockIdx.x, tid = threadIdx.x;
    float4* yr = reinterpret_cast<float4*>(y + (size_t)row * Ee);
    float4 v = yr[tid];
    float s = v.x + v.y + v.z + v.w;
    float q = v.x * v.x + v.y * v.y + v.z * v.z + v.w * v.w;
    __shared__ float sS[8], sQ[8];
    const int lane = tid & 31, wid = tid >> 5;
#pragma unroll
    for (int off = 16; off; off >>= 1) {
        s += __shfl_xor_sync(0xffffffffu, s, off);
        q += __shfl_xor_sync(0xffffffffu, q, off);
    }
    if (lane == 0) { sS[wid] = s; sQ[wid] = q; }
    __syncthreads();
    if (tid == 0) {
        float ts = 0.f, tq = 0.f;
#pragma unroll
        for (int i = 0; i < 8; i++) { ts += sS[i]; tq += sQ[i]; }
        sS[0] = ts; sQ[0] = tq;
    }
    __syncthreads();
    float mu = sS[0] * (1.f / 1024.f);
    float var = sQ[0] * (1.f / 1024.f) - mu * mu;
    float rstd = rsqrtf(var + 1e-5f);
    const float4 gm = reinterpret_cast<const float4*>(gamma)[tid];
    const float4 bt = reinterpret_cast<const float4*>(beta)[tid];
    float4 o;
    o.x = gm.x * (v.x - mu) * rstd + bt.x;
    o.y = gm.y * (v.y - mu) * rstd + bt.y;
    o.z = gm.z * (v.z - mu) * rstd + bt.z;
    o.w = gm.w * (v.w - mu) * rstd + bt.w;
    yr[tid] = o;
}

// ---------------- launch ----------------
extern "C" void kernel_launch(void* const* d_in, const int* in_sizes, int n_in,
                              void* d_out, int out_size) {
    const float* x    = (const float*)d_in[0];
    const float* ctxW = (const float*)d_in[1];
    const float* ctxb = (const float*)d_in[2];
    const float* qaW  = (const float*)d_in[3];
    const float* qab  = (const float*)d_in[4];
    const float* qbW  = (const float*)d_in[5];
    const float* qbb  = (const float*)d_in[6];
    const float* kaW  = (const float*)d_in[7];
    const float* kab  = (const float*)d_in[8];
    const float* kbW  = (const float*)d_in[9];
    const float* kbb  = (const float*)d_in[10];
    const float* vaW  = (const float*)d_in[11];
    const float* vab  = (const float*)d_in[12];
    const float* vbW  = (const float*)d_in[13];
    const float* vbb  = (const float*)d_in[14];
    const float* qeW  = (const float*)d_in[15];
    const float* qeb  = (const float*)d_in[16];
    const float* vqc  = (const float*)d_in[17];
    const float* ent  = (const float*)d_in[18];
    const float* outW = (const float*)d_in[19];
    const float* outb = (const float*)d_in[20];
    const float* gamma = (const float*)d_in[21];
    const float* beta  = (const float*)d_in[22];
    float* out = (float*)d_out;

    pack_kernel<<<512, 256>>>(ctxW, qaW, kaW, vaW, ctxb, qab, kab, vab);

    dim3 g1((NCAT + 127) / 128, NTOK / 128);
    gemm1_kernel<<<g1, 256>>>(x);

    tpa_feat_kernel<<<NTOK, 256>>>(qbW, qbb, kbW, kbb, vbW, vbb, qeW, qeb, vqc, ent);

    passA_kernel<<<Bb * KVv * NCH, 64>>>();
    passB_kernel<<<Bb * KVv, 64>>>();
    passC_kernel<<<Bb * KVv * NCH, 64>>>();

    dim3 g2(Ee / 128, NTOK / 128);
    gemm2_kernel<<<g2, 256>>>(outW, outb, x, out);

    ln_kernel<<<NTOK, 256>>>(out, gamma, beta);
}